// round 15
// baseline (speedup 1.0000x reference)
#include <cuda_runtime.h>
#include <cuda_bf16.h>
#include <math.h>
#include <stdint.h>

// Problem constants
#define BATCH 2
#define NQ 2048
#define NK 4096
#define DMODEL 512
#define NHEADS 8
#define DHEAD 64
#define HID 2048
#define MQ (BATCH * NQ)   // 4096
#define MK (BATCH * NK)   // 8192
#define NSPLIT 2

// ---------------- scratch ----------------------------------------------------
__device__ float g_q  [MQ * DMODEL];
__device__ float g_kv [MK * 1024];
__device__ float g_qkv[MQ * 1536];
__device__ float g_ctxA[MQ * DMODEL];       // split-0 numerator
__device__ float g_ctxB[MQ * DMODEL];       // split-1 numerator
__device__ float g_lsum[NSPLIT * MQ * NHEADS];
__device__ float g_cmb [MQ * DMODEL];       // combined tf32 bits
__device__ float g_xc [MQ * DMODEL];
__device__ float g_xn [MQ * DMODEL];
__device__ float g_y  [MQ * DMODEL];
__device__ float g_yn [MQ * DMODEL];
__device__ float g_h1 [MQ * HID];
__device__ unsigned g_wt[4194304];
__device__ float g_fb[3072];
__device__ unsigned g_xt[MQ * DMODEL];
__device__ unsigned g_ct[MK * DMODEL];

#define WT_CAQ  0
#define WT_CKV  262144
#define WT_SQKV 786432
#define WT_CAO  1572864
#define WT_SAO  1835008
#define WT_M1   2097152
#define WT_M2   3145728
#define FB_CAQ  0
#define FB_CKV  512
#define FB_SQKV 1536

// ---------------- helpers ----------------------------------------------------
__device__ __forceinline__ unsigned f2tf(float f) {
    unsigned u;
    asm("cvt.rna.tf32.f32 %0, %1;" : "=r"(u) : "f"(f));
    return u;
}
__device__ __forceinline__ float ex2(float x) {
    float y;
    asm("ex2.approx.f32 %0, %1;" : "=f"(y) : "f"(x));
    return y;
}
__device__ __forceinline__ void mma_tf32(float* d, const unsigned* a, const unsigned* b) {
    asm volatile(
        "mma.sync.aligned.m16n8k8.row.col.f32.tf32.tf32.f32 "
        "{%0,%1,%2,%3}, {%4,%5,%6,%7}, {%8,%9}, {%0,%1,%2,%3};"
        : "+f"(d[0]), "+f"(d[1]), "+f"(d[2]), "+f"(d[3])
        : "r"(a[0]), "r"(a[1]), "r"(a[2]), "r"(a[3]), "r"(b[0]), "r"(b[1]));
}
__device__ __forceinline__ unsigned smem_u32(const void* p) {
    return (unsigned)__cvta_generic_to_shared(p);
}
#define CP_ASYNC16(dst, src) \
    asm volatile("cp.async.cg.shared.global [%0], [%1], 16;\n" :: "r"(dst), "l"(src))
#define CP_COMMIT() asm volatile("cp.async.commit_group;\n" ::: "memory")
#define CP_WAIT1()  asm volatile("cp.async.wait_group 1;\n" ::: "memory")

// ---------------- fused pre-pass ---------------------------------------------
struct Seg {
    const float4* src;
    void* dst;
    int base;
    int n4;
    int outLD;
    int colOff;
    float scale;
    int mode;   // 0 flat tf32, 1 sectioned tf32 (src width 512), 2 float*scale
};
struct PrepArgs { Seg s[18]; int total; };

__global__ void prep_kernel(PrepArgs pa) {
    const int gid = blockIdx.x * 256 + threadIdx.x;
    if (gid >= pa.total) return;
    #pragma unroll 1
    for (int i = 0; i < 18; i++) {
        const Seg& sg = pa.s[i];
        if (gid < sg.base + sg.n4) {
            const int li = gid - sg.base;
            const float4 v = sg.src[li];
            if (sg.mode == 2) {
                ((float4*)sg.dst)[li] = make_float4(v.x * sg.scale, v.y * sg.scale,
                                                    v.z * sg.scale, v.w * sg.scale);
            } else {
                uint4 u;
                u.x = f2tf(v.x * sg.scale); u.y = f2tf(v.y * sg.scale);
                u.z = f2tf(v.z * sg.scale); u.w = f2tf(v.w * sg.scale);
                if (sg.mode == 1) {
                    const int k = li >> 7, n4 = li & 127;
                    *(uint4*)&((unsigned*)sg.dst)[(size_t)k * sg.outLD + sg.colOff + n4 * 4] = u;
                } else {
                    ((uint4*)sg.dst)[li] = u;
                }
            }
            return;
        }
    }
}

// ---------------- split-K combine: out = tf32((O0+O1)/(L0+L1)) ---------------
__global__ void combine_kernel(const float4* __restrict__ O0,
                               const float4* __restrict__ O1,
                               const float* __restrict__ L0,
                               const float* __restrict__ L1,
                               uint4* __restrict__ out) {
    const int gid = blockIdx.x * 256 + threadIdx.x;
    if (gid >= MQ * DMODEL / 4) return;
    const int idx = gid * 4;
    const int row = idx >> 9;
    const int h = (idx & 511) >> 6;
    const float inv = 1.0f / (L0[row * NHEADS + h] + L1[row * NHEADS + h]);
    const float4 a = O0[gid];
    const float4 c = O1[gid];
    uint4 u;
    u.x = f2tf((a.x + c.x) * inv);
    u.y = f2tf((a.y + c.y) * inv);
    u.z = f2tf((a.z + c.z) * inv);
    u.w = f2tf((a.w + c.w) * inv);
    out[gid] = u;
}

// ---------------- GEMM epilogue (shared) -------------------------------------
__device__ __forceinline__ void gemm_epilogue_frag(
    float* sv, const float* bias, const float* res, float* C,
    int r0, int c0, int N, int do_gelu, int out_tf32) {
    const float b0 = bias[c0], b1 = bias[c0 + 1];
    float v0 = sv[0] + b0, v1 = sv[1] + b1;
    float v2 = sv[2] + b0, v3 = sv[3] + b1;
    if (res) {
        const float2 r0v = *(const float2*)&res[(size_t)r0 * N + c0];
        const float2 r1v = *(const float2*)&res[(size_t)(r0 + 8) * N + c0];
        v0 += r0v.x; v1 += r0v.y; v2 += r1v.x; v3 += r1v.y;
    }
    if (do_gelu) {
        v0 = 0.5f * v0 * (1.0f + erff(v0 * 0.7071067811865476f));
        v1 = 0.5f * v1 * (1.0f + erff(v1 * 0.7071067811865476f));
        v2 = 0.5f * v2 * (1.0f + erff(v2 * 0.7071067811865476f));
        v3 = 0.5f * v3 * (1.0f + erff(v3 * 0.7071067811865476f));
    }
    if (out_tf32) {
        v0 = __uint_as_float(f2tf(v0));
        v1 = __uint_as_float(f2tf(v1));
        v2 = __uint_as_float(f2tf(v2));
        v3 = __uint_as_float(f2tf(v3));
    }
    *(float2*)&C[(size_t)r0 * N + c0]       = make_float2(v0, v1);
    *(float2*)&C[(size_t)(r0 + 8) * N + c0] = make_float2(v2, v3);
}

// ---------------- GEMM 128x128, 128 threads (R12) ----------------------------
#define AS_STRIDE 40
#define BS_STRIDE 132
#define A_BUF_W (128 * AS_STRIDE)
#define B_BUF_W (32 * BS_STRIDE)
#define STAGE_W (A_BUF_W + B_BUF_W)
#define GEMM_SMEM (2 * STAGE_W * 4)

__global__ void __launch_bounds__(128, 2)
tc_gemm(const unsigned* __restrict__ A, const unsigned* __restrict__ B,
        const float* __restrict__ bias, const float* __restrict__ res,
        float* __restrict__ C, int M, int N, int K,
        int do_gelu, int out_tf32) {
    extern __shared__ unsigned gsm[];
    const unsigned sb = smem_u32(gsm);

    const int tid = threadIdx.x, warp = tid >> 5, lane = tid & 31;
    const int g = lane >> 2, tig = lane & 3;
    const int wm = warp >> 1, wn = warp & 1;
    const int m0 = blockIdx.y * 128, n0 = blockIdx.x * 128;

    auto issue = [&](int t) {
        const unsigned ab = sb + ((t & 1) * STAGE_W) * 4;
        const unsigned bb = ab + A_BUF_W * 4;
        const int k0 = t * 32;
        #pragma unroll
        for (int p = 0; p < 8; p++) {
            const int c = p * 128 + tid;
            const int row = c >> 3, col = (c & 7) * 4;
            CP_ASYNC16(ab + (row * AS_STRIDE + col) * 4,
                       A + (size_t)(m0 + row) * K + k0 + col);
        }
        #pragma unroll
        for (int p = 0; p < 8; p++) {
            const int c = p * 128 + tid;
            const int row = c >> 5, col = (c & 31) * 4;
            CP_ASYNC16(bb + (row * BS_STRIDE + col) * 4,
                       B + (size_t)(k0 + row) * N + n0 + col);
        }
    };

    float s[4][8][4];
    #pragma unroll
    for (int mi = 0; mi < 4; mi++)
        #pragma unroll
        for (int nf = 0; nf < 8; nf++)
            #pragma unroll
            for (int v = 0; v < 4; v++) s[mi][nf][v] = 0.0f;

    const int T = K >> 5;
    issue(0); CP_COMMIT();
    issue(1); CP_COMMIT();

    for (int t = 0; t < T; t++) {
        CP_WAIT1();
        __syncthreads();
        const unsigned* As = gsm + (t & 1) * STAGE_W;
        const unsigned* Bs = As + A_BUF_W;

        #pragma unroll
        for (int kk = 0; kk < 4; kk++) {
            unsigned a[4][4], b[8][2];
            #pragma unroll
            for (int mi = 0; mi < 4; mi++) {
                const int rb = wm * 64 + mi * 16;
                const uint2 a0 = *(const uint2*)&As[(rb + g    ) * AS_STRIDE + kk * 8 + 2 * tig];
                const uint2 a1 = *(const uint2*)&As[(rb + g + 8) * AS_STRIDE + kk * 8 + 2 * tig];
                a[mi][0] = a0.x; a[mi][2] = a0.y;
                a[mi][1] = a1.x; a[mi][3] = a1.y;
            }
            #pragma unroll
            for (int nf = 0; nf < 8; nf++) {
                b[nf][0] = Bs[(kk * 8 + 2 * tig    ) * BS_STRIDE + wn * 64 + nf * 8 + g];
                b[nf][1] = Bs[(kk * 8 + 2 * tig + 1) * BS_STRIDE + wn * 64 + nf * 8 + g];
            }
            #pragma unroll
            for (int mi = 0; mi < 4; mi++)
                #pragma unroll
                for (int nf = 0; nf < 8; nf++)
                    mma_tf32(s[mi][nf], a[mi], b[nf]);
        }

        __syncthreads();
        if (t + 2 < T) issue(t + 2);
        CP_COMMIT();
    }

    #pragma unroll
    for (int mi = 0; mi < 4; mi++) {
        const int r0 = m0 + wm * 64 + mi * 16 + g;
        #pragma unroll
        for (int nf = 0; nf < 8; nf++)
            gemm_epilogue_frag(s[mi][nf], bias, res, C,
                               r0, n0 + wn * 64 + nf * 8 + 2 * tig, N,
                               do_gelu, out_tf32);
    }
}

// ---------------- Flash attention: split-K, 32-key tiles ---------------------
// grid.z = BATCH*NSPLIT (b = z % BATCH, split = z / BATCH). Each split covers
// kcount keys starting at split*kcount, writes partial numerator + row sums.
#define QS_STRIDE 72
#define KS_STRIDE 72
#define VS_STRIDE 68
#define Q_BUF_W  (128 * QS_STRIDE)
#define KV_BUF_W (32 * (KS_STRIDE + VS_STRIDE))
#define ATTN_SMEM ((Q_BUF_W + 2 * KV_BUF_W) * 4)   // 72704 B

__global__ void __launch_bounds__(128, 3)
attn_kernel(const float* __restrict__ Q,
            const float* __restrict__ Kg,
            const float* __restrict__ Vg,
            float* __restrict__ OA,     // split-0 numerator base
            float* __restrict__ OB,     // split-1 numerator base
            float* __restrict__ Lsum,   // [NSPLIT][MQ][NHEADS]
            int Nq, int Nk, int kcount, int ldq, int ldkv) {
    extern __shared__ unsigned sm[];
    const unsigned smem_base = smem_u32(sm);

    const int tid = threadIdx.x;
    const int warp = tid >> 5, lane = tid & 31;
    const int g = lane >> 2, tig = lane & 3;
    const int q0 = blockIdx.x * 128;
    const int h  = blockIdx.y;
    const int z  = blockIdx.z;
    const int b  = z % BATCH;
    const int split = z / BATCH;
    const int hoff = h * DHEAD;

    float* Op = split ? OB : OA;
    float* Lp = Lsum + (size_t)split * MQ * NHEADS;

    const size_t qrowbase = (size_t)b * Nq + q0 + warp * 32;
    const int nIter = kcount / 32;
    const int kbase = split * kcount;
    const size_t kvhead = (size_t)b * Nk * ldkv + hoff;

    {
        const size_t qg = ((size_t)b * Nq + q0) * ldq + hoff;
        #pragma unroll
        for (int p = 0; p < 16; p++) {
            const int c = p * 128 + tid;
            const int row = c >> 4, col = (c & 15) * 4;
            CP_ASYNC16(smem_base + (row * QS_STRIDE + col) * 4,
                       Q + qg + (size_t)row * ldq + col);
        }
    }

    auto issue_stage = [&](int st) {
        const unsigned buf = smem_base + (Q_BUF_W + (st & 1) * KV_BUF_W) * 4;
        const unsigned vbuf = buf + 32 * KS_STRIDE * 4;
        const size_t gk = kvhead + (size_t)(kbase + st * 32) * ldkv;
        #pragma unroll
        for (int p = 0; p < 4; p++) {
            const int c = p * 128 + tid;
            const int row = c >> 4, col = (c & 15) * 4;
            CP_ASYNC16(buf + (row * KS_STRIDE + col) * 4,
                       Kg + gk + (size_t)row * ldkv + col);
        }
        #pragma unroll
        for (int p = 0; p < 4; p++) {
            const int c = p * 128 + tid;
            const int row = c >> 4, col = (c & 15) * 4;
            CP_ASYNC16(vbuf + (row * VS_STRIDE + col) * 4,
                       Vg + gk + (size_t)row * ldkv + col);
        }
    };

    issue_stage(0); CP_COMMIT();
    if (nIter > 1) issue_stage(1);
    CP_COMMIT();

    float o[2][8][4];
    #pragma unroll
    for (int mi = 0; mi < 2; mi++)
        #pragma unroll
        for (int nf = 0; nf < 8; nf++)
            #pragma unroll
            for (int v = 0; v < 4; v++) o[mi][nf][v] = 0.0f;
    float lrow[2][2] = {{0.0f, 0.0f}, {0.0f, 0.0f}};

    const unsigned* Qs0 = sm + (warp * 32 + g) * QS_STRIDE;
    const unsigned* Qs1 = sm + (warp * 32 + 16 + g) * QS_STRIDE;

    for (int it = 0; it < nIter; it++) {
        CP_WAIT1();
        __syncthreads();

        const unsigned* Ks = sm + Q_BUF_W + (it & 1) * KV_BUF_W;
        const unsigned* Vs = Ks + 32 * KS_STRIDE;

        float s[2][4][4];
        #pragma unroll
        for (int mi = 0; mi < 2; mi++)
            #pragma unroll
            for (int nf = 0; nf < 4; nf++)
                #pragma unroll
                for (int v = 0; v < 4; v++) s[mi][nf][v] = 0.0f;

        #pragma unroll
        for (int kk = 0; kk < 8; kk++) {
            unsigned qa[2][4];
            {
                const uint2 q00 = *(const uint2*)&Qs0[kk * 8 + 2 * tig];
                const uint2 q01 = *(const uint2*)&Qs0[8 * QS_STRIDE + kk * 8 + 2 * tig];
                qa[0][0] = q00.x; qa[0][2] = q00.y;
                qa[0][1] = q01.x; qa[0][3] = q01.y;
                const uint2 q10 = *(const uint2*)&Qs1[kk * 8 + 2 * tig];
                const uint2 q11 = *(const uint2*)&Qs1[8 * QS_STRIDE + kk * 8 + 2 * tig];
                qa[1][0] = q10.x; qa[1][2] = q10.y;
                qa[1][1] = q11.x; qa[1][3] = q11.y;
            }
            #pragma unroll
            for (int nf = 0; nf < 4; nf++) {
                const uint2 kb = *(const uint2*)&Ks[(nf * 8 + g) * KS_STRIDE + kk * 8 + 2 * tig];
                unsigned bf[2] = {kb.x, kb.y};
                mma_tf32(s[0][nf], qa[0], bf);
                mma_tf32(s[1][nf], qa[1], bf);
            }
        }

        #pragma unroll
        for (int mi = 0; mi < 2; mi++) {
            #pragma unroll
            for (int nf = 0; nf < 4; nf++) {
                const float p0 = ex2(s[mi][nf][0]);
                const float p1 = ex2(s[mi][nf][1]);
                const float p2 = ex2(s[mi][nf][2]);
                const float p3 = ex2(s[mi][nf][3]);
                lrow[mi][0] += p0 + p1;
                lrow[mi][1] += p2 + p3;
                s[mi][nf][0] = __uint_as_float(f2tf(p0));
                s[mi][nf][1] = __uint_as_float(f2tf(p1));
                s[mi][nf][2] = __uint_as_float(f2tf(p2));
                s[mi][nf][3] = __uint_as_float(f2tf(p3));
            }
        }

        #pragma unroll
        for (int kk = 0; kk < 4; kk++) {
            unsigned a[2][4];
            #pragma unroll
            for (int mi = 0; mi < 2; mi++) {
                a[mi][0] = __float_as_uint(s[mi][kk][0]);
                a[mi][1] = __float_as_uint(s[mi][kk][2]);
                a[mi][2] = __float_as_uint(s[mi][kk][1]);
                a[mi][3] = __float_as_uint(s[mi][kk][3]);
            }
            #pragma unroll
            for (int nf = 0; nf < 8; nf++) {
                unsigned bf[2];
                bf[0] = Vs[(kk * 8 + 2 * tig    ) * VS_STRIDE + nf * 8 + g];
                bf[1] = Vs[(kk * 8 + 2 * tig + 1) * VS_STRIDE + nf * 8 + g];
                mma_tf32(o[0][nf], a[0], bf);
                mma_tf32(o[1][nf], a[1], bf);
            }
        }

        __syncthreads();
        if (it + 2 < nIter) issue_stage(it + 2);
        CP_COMMIT();
    }

    // reduce row sums across tig lanes (disjoint key partials)
    #pragma unroll
    for (int mi = 0; mi < 2; mi++)
        #pragma unroll
        for (int hh = 0; hh < 2; hh++) {
            lrow[mi][hh] += __shfl_xor_sync(0xffffffffu, lrow[mi][hh], 1);
            lrow[mi][hh] += __shfl_xor_sync(0xffffffffu, lrow[mi][hh], 2);
        }

    // write partial numerator (plain fp32) + row sums
    #pragma unroll
    for (int mi = 0; mi < 2; mi++) {
        float* op = Op + (qrowbase + mi * 16 + g) * DMODEL + hoff;
        #pragma unroll
        for (int nf = 0; nf < 8; nf++) {
            *(float2*)&op[nf * 8 + 2 * tig] = make_float2(o[mi][nf][0], o[mi][nf][1]);
            *(float2*)&op[(size_t)8 * DMODEL + nf * 8 + 2 * tig] =
                make_float2(o[mi][nf][2], o[mi][nf][3]);
        }
        if (tig == 0) {
            Lp[(qrowbase + mi * 16 + g) * NHEADS + h]     = lrow[mi][0];
            Lp[(qrowbase + mi * 16 + g + 8) * NHEADS + h] = lrow[mi][1];
        }
    }
}

// ---------------- LayerNorm (tf32-bit output) --------------------------------
__global__ void ln_kernel(const float* __restrict__ X,
                          const float* __restrict__ gam,
                          const float* __restrict__ bet,
                          float* __restrict__ Y, int otf) {
    const int row = blockIdx.x;
    const int t = threadIdx.x;
    const float* xr = X + (size_t)row * DMODEL;
    float v[4];
    float s = 0.0f, sq = 0.0f;
    #pragma unroll
    for (int i = 0; i < 4; i++) {
        v[i] = xr[t + i * 128];
        s += v[i];
        sq = fmaf(v[i], v[i], sq);
    }
    #pragma unroll
    for (int off = 1; off < 32; off <<= 1) {
        s  += __shfl_xor_sync(0xffffffffu, s, off);
        sq += __shfl_xor_sync(0xffffffffu, sq, off);
    }
    __shared__ float rs[4], rq[4];
    if ((t & 31) == 0) { rs[t >> 5] = s; rq[t >> 5] = sq; }
    __syncthreads();
    s  = rs[0] + rs[1] + rs[2] + rs[3];
    sq = rq[0] + rq[1] + rq[2] + rq[3];
    const float mean = s * (1.0f / DMODEL);
    const float var  = sq * (1.0f / DMODEL) - mean * mean;
    const float rstd = rsqrtf(var + 1e-5f);
    float* yr = Y + (size_t)row * DMODEL;
    #pragma unroll
    for (int i = 0; i < 4; i++) {
        const int c = t + i * 128;
        float val = (v[i] - mean) * rstd * gam[c] + bet[c];
        if (otf) val = __uint_as_float(f2tf(val));
        yr[c] = val;
    }
}

// ---------------- launcher ---------------------------------------------------
static void launch_tc(const void* A, const unsigned* B, const float* bias,
                      const float* res, float* C, int M, int N, int K,
                      int gelu, int otf) {
    dim3 grid(N / 128, M / 128);
    tc_gemm<<<grid, 128, GEMM_SMEM>>>((const unsigned*)A, B, bias, res, C,
                                      M, N, K, gelu, otf);
}

extern "C" void kernel_launch(void* const* d_in, const int* in_sizes, int n_in,
                              void* d_out, int out_size) {
    const float* x      = (const float*)d_in[0];
    const float* cross  = (const float*)d_in[1];
    const float* ca_wq  = (const float*)d_in[2];
    const float* ca_bq  = (const float*)d_in[3];
    const float* ca_wk  = (const float*)d_in[4];
    const float* ca_bk  = (const float*)d_in[5];
    const float* ca_wv  = (const float*)d_in[6];
    const float* ca_bv  = (const float*)d_in[7];
    const float* ca_wo  = (const float*)d_in[8];
    const float* ca_bo  = (const float*)d_in[9];
    const float* sa_wq  = (const float*)d_in[10];
    const float* sa_bq  = (const float*)d_in[11];
    const float* sa_wk  = (const float*)d_in[12];
    const float* sa_bk  = (const float*)d_in[13];
    const float* sa_wv  = (const float*)d_in[14];
    const float* sa_bv  = (const float*)d_in[15];
    const float* sa_wo  = (const float*)d_in[16];
    const float* sa_bo  = (const float*)d_in[17];
    const float* ln1_g  = (const float*)d_in[18];
    const float* ln1_b  = (const float*)d_in[19];
    const float* ln2_g  = (const float*)d_in[20];
    const float* ln2_b  = (const float*)d_in[21];
    const float* mlp_w1 = (const float*)d_in[22];
    const float* mlp_b1 = (const float*)d_in[23];
    const float* mlp_w2 = (const float*)d_in[24];
    const float* mlp_b2 = (const float*)d_in[25];
    float* out = (float*)d_out;

    const float SC = 0.18033688011112042f;   // 0.125 * log2(e)

    cudaFuncSetAttribute(attn_kernel, cudaFuncAttributeMaxDynamicSharedMemorySize,
                         ATTN_SMEM);
    cudaFuncSetAttribute(tc_gemm, cudaFuncAttributeMaxDynamicSharedMemorySize,
                         GEMM_SMEM);
    cudaFuncSetAttribute(attn_kernel, cudaFuncAttributePreferredSharedMemoryCarveout,
                         cudaSharedmemCarveoutMaxShared);
    cudaFuncSetAttribute(tc_gemm, cudaFuncAttributePreferredSharedMemoryCarveout,
                         cudaSharedmemCarveoutMaxShared);

    float *pq, *pkv, *pqkv, *pca, *pcb, *pls, *pcm, *pxc, *pxn, *py, *pyn, *ph1, *pfb;
    unsigned *pwt, *pxt, *pct;
    cudaGetSymbolAddress((void**)&pq,   g_q);
    cudaGetSymbolAddress((void**)&pkv,  g_kv);
    cudaGetSymbolAddress((void**)&pqkv, g_qkv);
    cudaGetSymbolAddress((void**)&pca,  g_ctxA);
    cudaGetSymbolAddress((void**)&pcb,  g_ctxB);
    cudaGetSymbolAddress((void**)&pls,  g_lsum);
    cudaGetSymbolAddress((void**)&pcm,  g_cmb);
    cudaGetSymbolAddress((void**)&pxc,  g_xc);
    cudaGetSymbolAddress((void**)&pxn,  g_xn);
    cudaGetSymbolAddress((void**)&py,   g_y);
    cudaGetSymbolAddress((void**)&pyn,  g_yn);
    cudaGetSymbolAddress((void**)&ph1,  g_h1);
    cudaGetSymbolAddress((void**)&pwt,  g_wt);
    cudaGetSymbolAddress((void**)&pfb,  g_fb);
    cudaGetSymbolAddress((void**)&pxt,  g_xt);
    cudaGetSymbolAddress((void**)&pct,  g_ct);

    // ---- single fused pre-pass ----
    {
        PrepArgs pa;
        int base = 0;
        auto add = [&](int i, const float* src, void* dst, int n4, int outLD,
                       int colOff, float scale, int mode) {
            pa.s[i] = Seg{(const float4*)src, dst, base, n4, outLD, colOff, scale, mode};
            base += n4;
        };
        add(0,  ca_wq,  pwt + WT_CAQ,  65536, 512, 0, SC, 1);
        add(1,  ca_wk,  pwt + WT_CKV,  65536, 1024, 0, 1.0f, 1);
        add(2,  ca_wv,  pwt + WT_CKV,  65536, 1024, 512, 1.0f, 1);
        add(3,  sa_wq,  pwt + WT_SQKV, 65536, 1536, 0, SC, 1);
        add(4,  sa_wk,  pwt + WT_SQKV, 65536, 1536, 512, 1.0f, 1);
        add(5,  sa_wv,  pwt + WT_SQKV, 65536, 1536, 1024, 1.0f, 1);
        add(6,  ca_wo,  pwt + WT_CAO,  65536, 0, 0, 1.0f, 0);
        add(7,  sa_wo,  pwt + WT_SAO,  65536, 0, 0, 1.0f, 0);
        add(8,  mlp_w1, pwt + WT_M1,   262144, 0, 0, 1.0f, 0);
        add(9,  mlp_w2, pwt + WT_M2,   262144, 0, 0, 1.0f, 0);
        add(10, x,      pxt,           524288, 0, 0, 1.0f, 0);
        add(11, cross,  pct,           1048576, 0, 0, 1.0f, 0);
        add(12, ca_bq,  pfb + FB_CAQ,         128, 0, 0, SC,   2);
        add(13, ca_bk,  pfb + FB_CKV,         128, 0, 0, 1.0f, 2);
        add(14, ca_bv,  pfb + FB_CKV + 512,   128, 0, 0, 1.0f, 2);
        add(15, sa_bq,  pfb + FB_SQKV,        128, 0, 0, SC,   2);
        add(16, sa_bk,  pfb + FB_SQKV + 512,  128, 0, 0, 1.0f, 2);
        add(17, sa_bv,  pfb + FB_SQKV + 1024, 128, 0, 0, 1.0f, 2);
        pa.total = base;
        prep_kernel<<<(pa.total + 255) / 256, 256>>>(pa);
    }

    const int CMB_BLOCKS = (MQ * DMODEL / 4 + 255) / 256;

    // ---- cross attention ----
    launch_tc(pxt, pwt + WT_CAQ, pfb + FB_CAQ, nullptr, pq, MQ, 512, DMODEL, 0, 1);
    launch_tc(pct, pwt + WT_CKV, pfb + FB_CKV, nullptr, pkv, MK, 1024, DMODEL, 0, 1);
    {
        dim3 grid(NQ / 128, NHEADS, BATCH * NSPLIT);
        attn_kernel<<<grid, 128, ATTN_SMEM>>>(pq, pkv, pkv + 512, pca, pcb, pls,
                                              NQ, NK, NK / NSPLIT, 512, 1024);
    }
    combine_kernel<<<CMB_BLOCKS, 256>>>((const float4*)pca, (const float4*)pcb,
                                        pls, pls + MQ * NHEADS, (uint4*)pcm);
    launch_tc(pcm, pwt + WT_CAO, ca_bo, nullptr, pxc, MQ, DMODEL, DMODEL, 0, 0);

    // ---- LN1 + self attention ----
    ln_kernel<<<MQ, 128>>>(pxc, ln1_g, ln1_b, pxn, 1);
    launch_tc(pxn, pwt + WT_SQKV, pfb + FB_SQKV, nullptr, pqkv, MQ, 1536, DMODEL, 0, 1);
    {
        dim3 grid(NQ / 128, NHEADS, BATCH * NSPLIT);
        attn_kernel<<<grid, 128, ATTN_SMEM>>>(pqkv, pqkv + 512, pqkv + 1024,
                                              pca, pcb, pls,
                                              NQ, NQ, NQ / NSPLIT, 1536, 1536);
    }
    combine_kernel<<<CMB_BLOCKS, 256>>>((const float4*)pca, (const float4*)pcb,
                                        pls, pls + MQ * NHEADS, (uint4*)pcm);
    launch_tc(pcm, pwt + WT_SAO, sa_bo, pxc, py, MQ, DMODEL, DMODEL, 0, 0);

    // ---- LN2 + MLP ----
    ln_kernel<<<MQ, 128>>>(py, ln2_g, ln2_b, pyn, 1);
    launch_tc(pyn, pwt + WT_M1, mlp_b1, nullptr, ph1, MQ, HID, DMODEL, 1, 1);
    launch_tc(ph1, pwt + WT_M2, mlp_b2, py, out, MQ, DMODEL, HID, 0, 0);
}

// round 17
// speedup vs baseline: 1.2749x; 1.2749x over previous
#include <cuda_runtime.h>
#include <cuda_fp16.h>
#include <math.h>
#include <stdint.h>

// Problem constants
#define BATCH 2
#define NQ 2048
#define NK 4096
#define DMODEL 512
#define NHEADS 8
#define DHEAD 64
#define HID 2048
#define MQ (BATCH * NQ)   // 4096
#define MK (BATCH * NK)   // 8192
#define NSPLIT 2

// ---------------- scratch ----------------------------------------------------
__device__ __half g_qh  [MQ * DMODEL];       // cross Q (fp16, pre-scaled)
__device__ __half g_kvh [MK * 1024];         // cross K|V fused (fp16)
__device__ __half g_qkvh[MQ * 1536];         // self Q|K|V fused (fp16)
__device__ float g_ctxA[MQ * DMODEL];
__device__ float g_ctxB[MQ * DMODEL];
__device__ float g_lsum[NSPLIT * MQ * NHEADS];
__device__ float g_cmb [MQ * DMODEL];        // combined tf32 bits
__device__ float g_xc [MQ * DMODEL];
__device__ float g_xn [MQ * DMODEL];
__device__ float g_y  [MQ * DMODEL];
__device__ float g_yn [MQ * DMODEL];
__device__ float g_h1 [MQ * HID];
__device__ unsigned g_wt[4194304];
__device__ float g_fb[3072];
__device__ unsigned g_xt[MQ * DMODEL];
__device__ unsigned g_ct[MK * DMODEL];

#define WT_CAQ  0
#define WT_CKV  262144
#define WT_SQKV 786432
#define WT_CAO  1572864
#define WT_SAO  1835008
#define WT_M1   2097152
#define WT_M2   3145728
#define FB_CAQ  0
#define FB_CKV  512
#define FB_SQKV 1536

// ---------------- helpers ----------------------------------------------------
__device__ __forceinline__ unsigned f2tf(float f) {
    unsigned u;
    asm("cvt.rna.tf32.f32 %0, %1;" : "=r"(u) : "f"(f));
    return u;
}
__device__ __forceinline__ float ex2(float x) {
    float y;
    asm("ex2.approx.f32 %0, %1;" : "=f"(y) : "f"(x));
    return y;
}
__device__ __forceinline__ unsigned h2u(__half2 h) {
    unsigned u;
    asm("mov.b32 %0, %1;" : "=r"(u) : "r"(*(unsigned*)&h));
    return u;
}
__device__ __forceinline__ void mma_tf32(float* d, const unsigned* a, const unsigned* b) {
    asm volatile(
        "mma.sync.aligned.m16n8k8.row.col.f32.tf32.tf32.f32 "
        "{%0,%1,%2,%3}, {%4,%5,%6,%7}, {%8,%9}, {%0,%1,%2,%3};"
        : "+f"(d[0]), "+f"(d[1]), "+f"(d[2]), "+f"(d[3])
        : "r"(a[0]), "r"(a[1]), "r"(a[2]), "r"(a[3]), "r"(b[0]), "r"(b[1]));
}
__device__ __forceinline__ void mma_f16(float* d, const unsigned* a, const unsigned* b) {
    asm volatile(
        "mma.sync.aligned.m16n8k16.row.col.f32.f16.f16.f32 "
        "{%0,%1,%2,%3}, {%4,%5,%6,%7}, {%8,%9}, {%0,%1,%2,%3};"
        : "+f"(d[0]), "+f"(d[1]), "+f"(d[2]), "+f"(d[3])
        : "r"(a[0]), "r"(a[1]), "r"(a[2]), "r"(a[3]), "r"(b[0]), "r"(b[1]));
}
__device__ __forceinline__ unsigned smem_u32(const void* p) {
    return (unsigned)__cvta_generic_to_shared(p);
}
#define CP_ASYNC16(dst, src) \
    asm volatile("cp.async.cg.shared.global [%0], [%1], 16;\n" :: "r"(dst), "l"(src))
#define CP_COMMIT() asm volatile("cp.async.commit_group;\n" ::: "memory")
#define CP_WAIT1()  asm volatile("cp.async.wait_group 1;\n" ::: "memory")

// ---------------- fused pre-pass ---------------------------------------------
struct Seg {
    const float4* src;
    void* dst;
    int base;
    int n4;
    int outLD;
    int colOff;
    float scale;
    int mode;   // 0 flat tf32, 1 sectioned tf32 (src width 512), 2 float*scale
};
struct PrepArgs { Seg s[18]; int total; };

__global__ void prep_kernel(PrepArgs pa) {
    const int gid = blockIdx.x * 256 + threadIdx.x;
    if (gid >= pa.total) return;
    #pragma unroll 1
    for (int i = 0; i < 18; i++) {
        const Seg& sg = pa.s[i];
        if (gid < sg.base + sg.n4) {
            const int li = gid - sg.base;
            const float4 v = sg.src[li];
            if (sg.mode == 2) {
                ((float4*)sg.dst)[li] = make_float4(v.x * sg.scale, v.y * sg.scale,
                                                    v.z * sg.scale, v.w * sg.scale);
            } else {
                uint4 u;
                u.x = f2tf(v.x * sg.scale); u.y = f2tf(v.y * sg.scale);
                u.z = f2tf(v.z * sg.scale); u.w = f2tf(v.w * sg.scale);
                if (sg.mode == 1) {
                    const int k = li >> 7, n4 = li & 127;
                    *(uint4*)&((unsigned*)sg.dst)[(size_t)k * sg.outLD + sg.colOff + n4 * 4] = u;
                } else {
                    ((uint4*)sg.dst)[li] = u;
                }
            }
            return;
        }
    }
}

// ---------------- split-K combine: out = tf32((O0+O1)/(L0+L1)) ---------------
__global__ void combine_kernel(const float4* __restrict__ O0,
                               const float4* __restrict__ O1,
                               const float* __restrict__ L0,
                               const float* __restrict__ L1,
                               uint4* __restrict__ out) {
    const int gid = blockIdx.x * 256 + threadIdx.x;
    if (gid >= MQ * DMODEL / 4) return;
    const int idx = gid * 4;
    const int row = idx >> 9;
    const int h = (idx & 511) >> 6;
    const float inv = 1.0f / (L0[row * NHEADS + h] + L1[row * NHEADS + h]);
    const float4 a = O0[gid];
    const float4 c = O1[gid];
    uint4 u;
    u.x = f2tf((a.x + c.x) * inv);
    u.y = f2tf((a.y + c.y) * inv);
    u.z = f2tf((a.z + c.z) * inv);
    u.w = f2tf((a.w + c.w) * inv);
    out[gid] = u;
}

// ---------------- GEMM epilogue (shared) -------------------------------------
// out_mode: 0 = fp32, 1 = tf32 bits, 2 = fp16
__device__ __forceinline__ void gemm_epilogue_frag(
    float* sv, const float* bias, const float* res, void* C,
    int r0, int c0, int N, int do_gelu, int out_mode) {
    const float b0 = bias[c0], b1 = bias[c0 + 1];
    float v0 = sv[0] + b0, v1 = sv[1] + b1;
    float v2 = sv[2] + b0, v3 = sv[3] + b1;
    if (res) {
        const float2 r0v = *(const float2*)&res[(size_t)r0 * N + c0];
        const float2 r1v = *(const float2*)&res[(size_t)(r0 + 8) * N + c0];
        v0 += r0v.x; v1 += r0v.y; v2 += r1v.x; v3 += r1v.y;
    }
    if (do_gelu) {
        v0 = 0.5f * v0 * (1.0f + erff(v0 * 0.7071067811865476f));
        v1 = 0.5f * v1 * (1.0f + erff(v1 * 0.7071067811865476f));
        v2 = 0.5f * v2 * (1.0f + erff(v2 * 0.7071067811865476f));
        v3 = 0.5f * v3 * (1.0f + erff(v3 * 0.7071067811865476f));
    }
    if (out_mode == 2) {
        __half* Ch = (__half*)C;
        *(__half2*)&Ch[(size_t)r0 * N + c0]       = __floats2half2_rn(v0, v1);
        *(__half2*)&Ch[(size_t)(r0 + 8) * N + c0] = __floats2half2_rn(v2, v3);
        return;
    }
    if (out_mode == 1) {
        v0 = __uint_as_float(f2tf(v0));
        v1 = __uint_as_float(f2tf(v1));
        v2 = __uint_as_float(f2tf(v2));
        v3 = __uint_as_float(f2tf(v3));
    }
    float* Cf = (float*)C;
    *(float2*)&Cf[(size_t)r0 * N + c0]       = make_float2(v0, v1);
    *(float2*)&Cf[(size_t)(r0 + 8) * N + c0] = make_float2(v2, v3);
}

// ---------------- GEMM 128x128, 128 threads (tf32 in, flexible out) ----------
#define AS_STRIDE 40
#define BS_STRIDE 132
#define A_BUF_W (128 * AS_STRIDE)
#define B_BUF_W (32 * BS_STRIDE)
#define STAGE_W (A_BUF_W + B_BUF_W)
#define GEMM_SMEM (2 * STAGE_W * 4)

__global__ void __launch_bounds__(128, 2)
tc_gemm(const unsigned* __restrict__ A, const unsigned* __restrict__ B,
        const float* __restrict__ bias, const float* __restrict__ res,
        void* __restrict__ C, int M, int N, int K,
        int do_gelu, int out_mode) {
    extern __shared__ unsigned gsm[];
    const unsigned sb = smem_u32(gsm);

    const int tid = threadIdx.x, warp = tid >> 5, lane = tid & 31;
    const int g = lane >> 2, tig = lane & 3;
    const int wm = warp >> 1, wn = warp & 1;
    const int m0 = blockIdx.y * 128, n0 = blockIdx.x * 128;

    auto issue = [&](int t) {
        const unsigned ab = sb + ((t & 1) * STAGE_W) * 4;
        const unsigned bb = ab + A_BUF_W * 4;
        const int k0 = t * 32;
        #pragma unroll
        for (int p = 0; p < 8; p++) {
            const int c = p * 128 + tid;
            const int row = c >> 3, col = (c & 7) * 4;
            CP_ASYNC16(ab + (row * AS_STRIDE + col) * 4,
                       A + (size_t)(m0 + row) * K + k0 + col);
        }
        #pragma unroll
        for (int p = 0; p < 8; p++) {
            const int c = p * 128 + tid;
            const int row = c >> 5, col = (c & 31) * 4;
            CP_ASYNC16(bb + (row * BS_STRIDE + col) * 4,
                       B + (size_t)(k0 + row) * N + n0 + col);
        }
    };

    float s[4][8][4];
    #pragma unroll
    for (int mi = 0; mi < 4; mi++)
        #pragma unroll
        for (int nf = 0; nf < 8; nf++)
            #pragma unroll
            for (int v = 0; v < 4; v++) s[mi][nf][v] = 0.0f;

    const int T = K >> 5;
    issue(0); CP_COMMIT();
    issue(1); CP_COMMIT();

    for (int t = 0; t < T; t++) {
        CP_WAIT1();
        __syncthreads();
        const unsigned* As = gsm + (t & 1) * STAGE_W;
        const unsigned* Bs = As + A_BUF_W;

        #pragma unroll
        for (int kk = 0; kk < 4; kk++) {
            unsigned a[4][4], b[8][2];
            #pragma unroll
            for (int mi = 0; mi < 4; mi++) {
                const int rb = wm * 64 + mi * 16;
                const uint2 a0 = *(const uint2*)&As[(rb + g    ) * AS_STRIDE + kk * 8 + 2 * tig];
                const uint2 a1 = *(const uint2*)&As[(rb + g + 8) * AS_STRIDE + kk * 8 + 2 * tig];
                a[mi][0] = a0.x; a[mi][2] = a0.y;
                a[mi][1] = a1.x; a[mi][3] = a1.y;
            }
            #pragma unroll
            for (int nf = 0; nf < 8; nf++) {
                b[nf][0] = Bs[(kk * 8 + 2 * tig    ) * BS_STRIDE + wn * 64 + nf * 8 + g];
                b[nf][1] = Bs[(kk * 8 + 2 * tig + 1) * BS_STRIDE + wn * 64 + nf * 8 + g];
            }
            #pragma unroll
            for (int mi = 0; mi < 4; mi++)
                #pragma unroll
                for (int nf = 0; nf < 8; nf++)
                    mma_tf32(s[mi][nf], a[mi], b[nf]);
        }

        __syncthreads();
        if (t + 2 < T) issue(t + 2);
        CP_COMMIT();
    }

    #pragma unroll
    for (int mi = 0; mi < 4; mi++) {
        const int r0 = m0 + wm * 64 + mi * 16 + g;
        #pragma unroll
        for (int nf = 0; nf < 8; nf++)
            gemm_epilogue_frag(s[mi][nf], bias, res, C,
                               r0, n0 + wn * 64 + nf * 8 + 2 * tig, N,
                               do_gelu, out_mode);
    }
}

// ---------------- Flash attention: fp16 operands, split-K, 32-key tiles ------
// Q/K/V fp16 in gmem. Q in smem; K/V double-buffered. m16n8k16 fp16 MMA.
// P A-frags = half2 packs of S C-frags; V b-frags via ldmatrix.x2.trans.
#define QS2 72   // halves
#define KS2 72
#define VS2 72
#define Q_BYTES  (128 * QS2 * 2)                   // 18432
#define K_BYTES  (32 * KS2 * 2)                    // 4608
#define V_BYTES  (32 * VS2 * 2)                    // 4608
#define KV_BYTES (K_BYTES + V_BYTES)               // 9216
#define ATTN_SMEM (Q_BYTES + 2 * KV_BYTES)         // 36864

__global__ void __launch_bounds__(128, 3)
attn_kernel(const __half* __restrict__ Q,
            const __half* __restrict__ Kg,
            const __half* __restrict__ Vg,
            float* __restrict__ OA,
            float* __restrict__ OB,
            float* __restrict__ Lsum,
            int Nq, int Nk, int kcount, int ldq, int ldkv) {
    extern __shared__ __half hsm[];
    const unsigned smem_base = smem_u32(hsm);

    const int tid = threadIdx.x;
    const int warp = tid >> 5, lane = tid & 31;
    const int g = lane >> 2, tig = lane & 3;
    const int q0 = blockIdx.x * 128;
    const int h  = blockIdx.y;
    const int z  = blockIdx.z;
    const int b  = z % BATCH;
    const int split = z / BATCH;
    const int hoff = h * DHEAD;

    float* Op = split ? OB : OA;
    float* Lp = Lsum + (size_t)split * MQ * NHEADS;

    const size_t qrowbase = (size_t)b * Nq + q0 + warp * 32;
    const int nIter = kcount / 32;
    const int kbase = split * kcount;
    const size_t kvhead = (size_t)b * Nk * ldkv + hoff;

    // Q tile -> smem (fp16, 8-half chunks)
    {
        const size_t qg = ((size_t)b * Nq + q0) * ldq + hoff;
        #pragma unroll
        for (int p = 0; p < 8; p++) {
            const int c = p * 128 + tid;
            const int row = c >> 3, col8 = (c & 7) * 8;
            CP_ASYNC16(smem_base + (row * QS2 + col8) * 2,
                       Q + qg + (size_t)row * ldq + col8);
        }
    }

    auto issue_stage = [&](int st) {
        const unsigned kb0 = smem_base + Q_BYTES + (st & 1) * KV_BYTES;
        const unsigned vb0 = kb0 + K_BYTES;
        const size_t gk = kvhead + (size_t)(kbase + st * 32) * ldkv;
        #pragma unroll
        for (int p = 0; p < 2; p++) {
            const int c = p * 128 + tid;
            const int row = c >> 3, col8 = (c & 7) * 8;
            CP_ASYNC16(kb0 + (row * KS2 + col8) * 2,
                       Kg + gk + (size_t)row * ldkv + col8);
        }
        #pragma unroll
        for (int p = 0; p < 2; p++) {
            const int c = p * 128 + tid;
            const int row = c >> 3, col8 = (c & 7) * 8;
            CP_ASYNC16(vb0 + (row * VS2 + col8) * 2,
                       Vg + gk + (size_t)row * ldkv + col8);
        }
    };

    issue_stage(0); CP_COMMIT();
    if (nIter > 1) issue_stage(1);
    CP_COMMIT();

    float o[2][8][4];
    #pragma unroll
    for (int mi = 0; mi < 2; mi++)
        #pragma unroll
        for (int nf = 0; nf < 8; nf++)
            #pragma unroll
            for (int v = 0; v < 4; v++) o[mi][nf][v] = 0.0f;
    float lrow[2][2] = {{0.0f, 0.0f}, {0.0f, 0.0f}};

    const __half* Qs0 = hsm + (warp * 32 + g) * QS2;
    const __half* Qs1 = Qs0 + 16 * QS2;

    for (int it = 0; it < nIter; it++) {
        CP_WAIT1();
        __syncthreads();

        const __half* Ks = hsm + (Q_BYTES / 2) + (it & 1) * (KV_BYTES / 2);
        const unsigned vbase = smem_base + Q_BYTES + (it & 1) * KV_BYTES + K_BYTES;

        float s[2][4][4];
        #pragma unroll
        for (int mi = 0; mi < 2; mi++)
            #pragma unroll
            for (int nf = 0; nf < 4; nf++)
                #pragma unroll
                for (int v = 0; v < 4; v++) s[mi][nf][v] = 0.0f;

        // S = Q K^T : d=64 -> 4 k16 steps; 4 key-groups of 8
        #pragma unroll
        for (int ks = 0; ks < 4; ks++) {
            unsigned qa[2][4];
            qa[0][0] = *(const unsigned*)&Qs0[ks * 16 + 2 * tig];
            qa[0][1] = *(const unsigned*)&Qs0[8 * QS2 + ks * 16 + 2 * tig];
            qa[0][2] = *(const unsigned*)&Qs0[ks * 16 + 2 * tig + 8];
            qa[0][3] = *(const unsigned*)&Qs0[8 * QS2 + ks * 16 + 2 * tig + 8];
            qa[1][0] = *(const unsigned*)&Qs1[ks * 16 + 2 * tig];
            qa[1][1] = *(const unsigned*)&Qs1[8 * QS2 + ks * 16 + 2 * tig];
            qa[1][2] = *(const unsigned*)&Qs1[ks * 16 + 2 * tig + 8];
            qa[1][3] = *(const unsigned*)&Qs1[8 * QS2 + ks * 16 + 2 * tig + 8];
            #pragma unroll
            for (int nf = 0; nf < 4; nf++) {
                unsigned bf[2];
                bf[0] = *(const unsigned*)&Ks[(nf * 8 + g) * KS2 + ks * 16 + 2 * tig];
                bf[1] = *(const unsigned*)&Ks[(nf * 8 + g) * KS2 + ks * 16 + 2 * tig + 8];
                mma_f16(s[0][nf], qa[0], bf);
                mma_f16(s[1][nf], qa[1], bf);
            }
        }

        // softmax (no shift): P = exp2(S); pack P to half2 A-frag regs
        unsigned ph[2][4][2];
        #pragma unroll
        for (int mi = 0; mi < 2; mi++) {
            #pragma unroll
            for (int nf = 0; nf < 4; nf++) {
                const float p0 = ex2(s[mi][nf][0]);
                const float p1 = ex2(s[mi][nf][1]);
                const float p2 = ex2(s[mi][nf][2]);
                const float p3 = ex2(s[mi][nf][3]);
                lrow[mi][0] += p0 + p1;
                lrow[mi][1] += p2 + p3;
                ph[mi][nf][0] = h2u(__floats2half2_rn(p0, p1));
                ph[mi][nf][1] = h2u(__floats2half2_rn(p2, p3));
            }
        }

        // O += P @ V : 2 k16 steps over 32 keys; V b-frags via ldmatrix.trans
        #pragma unroll
        for (int kb = 0; kb < 2; kb++) {
            unsigned a[2][4];
            #pragma unroll
            for (int mi = 0; mi < 2; mi++) {
                a[mi][0] = ph[mi][2 * kb][0];
                a[mi][1] = ph[mi][2 * kb][1];
                a[mi][2] = ph[mi][2 * kb + 1][0];
                a[mi][3] = ph[mi][2 * kb + 1][1];
            }
            const unsigned vrow = vbase + ((kb * 16 + (lane & 15)) * VS2) * 2;
            #pragma unroll
            for (int nf = 0; nf < 8; nf++) {
                unsigned b0, b1;
                asm volatile(
                    "ldmatrix.sync.aligned.m8n8.x2.trans.shared.b16 {%0,%1}, [%2];"
                    : "=r"(b0), "=r"(b1) : "r"(vrow + nf * 16));
                unsigned bf[2] = {b0, b1};
                mma_f16(o[0][nf], a[0], bf);
                mma_f16(o[1][nf], a[1], bf);
            }
        }

        __syncthreads();
        if (it + 2 < nIter) issue_stage(it + 2);
        CP_COMMIT();
    }

    // reduce row sums across tig lanes
    #pragma unroll
    for (int mi = 0; mi < 2; mi++)
        #pragma unroll
        for (int hh = 0; hh < 2; hh++) {
            lrow[mi][hh] += __shfl_xor_sync(0xffffffffu, lrow[mi][hh], 1);
            lrow[mi][hh] += __shfl_xor_sync(0xffffffffu, lrow[mi][hh], 2);
        }

    // write partial numerator (fp32) + row sums
    #pragma unroll
    for (int mi = 0; mi < 2; mi++) {
        float* op = Op + (qrowbase + mi * 16 + g) * DMODEL + hoff;
        #pragma unroll
        for (int nf = 0; nf < 8; nf++) {
            *(float2*)&op[nf * 8 + 2 * tig] = make_float2(o[mi][nf][0], o[mi][nf][1]);
            *(float2*)&op[(size_t)8 * DMODEL + nf * 8 + 2 * tig] =
                make_float2(o[mi][nf][2], o[mi][nf][3]);
        }
        if (tig == 0) {
            Lp[(qrowbase + mi * 16 + g) * NHEADS + h]     = lrow[mi][0];
            Lp[(qrowbase + mi * 16 + g + 8) * NHEADS + h] = lrow[mi][1];
        }
    }
}

// ---------------- LayerNorm (tf32-bit output) --------------------------------
__global__ void ln_kernel(const float* __restrict__ X,
                          const float* __restrict__ gam,
                          const float* __restrict__ bet,
                          float* __restrict__ Y, int otf) {
    const int row = blockIdx.x;
    const int t = threadIdx.x;
    const float* xr = X + (size_t)row * DMODEL;
    float v[4];
    float s = 0.0f, sq = 0.0f;
    #pragma unroll
    for (int i = 0; i < 4; i++) {
        v[i] = xr[t + i * 128];
        s += v[i];
        sq = fmaf(v[i], v[i], sq);
    }
    #pragma unroll
    for (int off = 1; off < 32; off <<= 1) {
        s  += __shfl_xor_sync(0xffffffffu, s, off);
        sq += __shfl_xor_sync(0xffffffffu, sq, off);
    }
    __shared__ float rs[4], rq[4];
    if ((t & 31) == 0) { rs[t >> 5] = s; rq[t >> 5] = sq; }
    __syncthreads();
    s  = rs[0] + rs[1] + rs[2] + rs[3];
    sq = rq[0] + rq[1] + rq[2] + rq[3];
    const float mean = s * (1.0f / DMODEL);
    const float var  = sq * (1.0f / DMODEL) - mean * mean;
    const float rstd = rsqrtf(var + 1e-5f);
    float* yr = Y + (size_t)row * DMODEL;
    #pragma unroll
    for (int i = 0; i < 4; i++) {
        const int c = t + i * 128;
        float val = (v[i] - mean) * rstd * gam[c] + bet[c];
        if (otf) val = __uint_as_float(f2tf(val));
        yr[c] = val;
    }
}

// ---------------- launcher ---------------------------------------------------
static void launch_tc(const void* A, const unsigned* B, const float* bias,
                      const float* res, void* C, int M, int N, int K,
                      int gelu, int omode) {
    dim3 grid(N / 128, M / 128);
    tc_gemm<<<grid, 128, GEMM_SMEM>>>((const unsigned*)A, B, bias, res, C,
                                      M, N, K, gelu, omode);
}

extern "C" void kernel_launch(void* const* d_in, const int* in_sizes, int n_in,
                              void* d_out, int out_size) {
    const float* x      = (const float*)d_in[0];
    const float* cross  = (const float*)d_in[1];
    const float* ca_wq  = (const float*)d_in[2];
    const float* ca_bq  = (const float*)d_in[3];
    const float* ca_wk  = (const float*)d_in[4];
    const float* ca_bk  = (const float*)d_in[5];
    const float* ca_wv  = (const float*)d_in[6];
    const float* ca_bv  = (const float*)d_in[7];
    const float* ca_wo  = (const float*)d_in[8];
    const float* ca_bo  = (const float*)d_in[9];
    const float* sa_wq  = (const float*)d_in[10];
    const float* sa_bq  = (const float*)d_in[11];
    const float* sa_wk  = (const float*)d_in[12];
    const float* sa_bk  = (const float*)d_in[13];
    const float* sa_wv  = (const float*)d_in[14];
    const float* sa_bv  = (const float*)d_in[15];
    const float* sa_wo  = (const float*)d_in[16];
    const float* sa_bo  = (const float*)d_in[17];
    const float* ln1_g  = (const float*)d_in[18];
    const float* ln1_b  = (const float*)d_in[19];
    const float* ln2_g  = (const float*)d_in[20];
    const float* ln2_b  = (const float*)d_in[21];
    const float* mlp_w1 = (const float*)d_in[22];
    const float* mlp_b1 = (const float*)d_in[23];
    const float* mlp_w2 = (const float*)d_in[24];
    const float* mlp_b2 = (const float*)d_in[25];
    float* out = (float*)d_out;

    const float SC = 0.18033688011112042f;   // 0.125 * log2(e)

    cudaFuncSetAttribute(attn_kernel, cudaFuncAttributeMaxDynamicSharedMemorySize,
                         ATTN_SMEM);
    cudaFuncSetAttribute(tc_gemm, cudaFuncAttributeMaxDynamicSharedMemorySize,
                         GEMM_SMEM);
    cudaFuncSetAttribute(attn_kernel, cudaFuncAttributePreferredSharedMemoryCarveout,
                         cudaSharedmemCarveoutMaxShared);
    cudaFuncSetAttribute(tc_gemm, cudaFuncAttributePreferredSharedMemoryCarveout,
                         cudaSharedmemCarveoutMaxShared);

    __half *pqh, *pkvh, *pqkvh;
    float *pca, *pcb, *pls, *pcm, *pxc, *pxn, *py, *pyn, *ph1, *pfb;
    unsigned *pwt, *pxt, *pct;
    cudaGetSymbolAddress((void**)&pqh,   g_qh);
    cudaGetSymbolAddress((void**)&pkvh,  g_kvh);
    cudaGetSymbolAddress((void**)&pqkvh, g_qkvh);
    cudaGetSymbolAddress((void**)&pca,  g_ctxA);
    cudaGetSymbolAddress((void**)&pcb,  g_ctxB);
    cudaGetSymbolAddress((void**)&pls,  g_lsum);
    cudaGetSymbolAddress((void**)&pcm,  g_cmb);
    cudaGetSymbolAddress((void**)&pxc,  g_xc);
    cudaGetSymbolAddress((void**)&pxn,  g_xn);
    cudaGetSymbolAddress((void**)&py,   g_y);
    cudaGetSymbolAddress((void**)&pyn,  g_yn);
    cudaGetSymbolAddress((void**)&ph1,  g_h1);
    cudaGetSymbolAddress((void**)&pwt,  g_wt);
    cudaGetSymbolAddress((void**)&pfb,  g_fb);
    cudaGetSymbolAddress((void**)&pxt,  g_xt);
    cudaGetSymbolAddress((void**)&pct,  g_ct);

    // ---- single fused pre-pass ----
    {
        PrepArgs pa;
        int base = 0;
        auto add = [&](int i, const float* src, void* dst, int n4, int outLD,
                       int colOff, float scale, int mode) {
            pa.s[i] = Seg{(const float4*)src, dst, base, n4, outLD, colOff, scale, mode};
            base += n4;
        };
        add(0,  ca_wq,  pwt + WT_CAQ,  65536, 512, 0, SC, 1);
        add(1,  ca_wk,  pwt + WT_CKV,  65536, 1024, 0, 1.0f, 1);
        add(2,  ca_wv,  pwt + WT_CKV,  65536, 1024, 512, 1.0f, 1);
        add(3,  sa_wq,  pwt + WT_SQKV, 65536, 1536, 0, SC, 1);
        add(4,  sa_wk,  pwt + WT_SQKV, 65536, 1536, 512, 1.0f, 1);
        add(5,  sa_wv,  pwt + WT_SQKV, 65536, 1536, 1024, 1.0f, 1);
        add(6,  ca_wo,  pwt + WT_CAO,  65536, 0, 0, 1.0f, 0);
        add(7,  sa_wo,  pwt + WT_SAO,  65536, 0, 0, 1.0f, 0);
        add(8,  mlp_w1, pwt + WT_M1,   262144, 0, 0, 1.0f, 0);
        add(9,  mlp_w2, pwt + WT_M2,   262144, 0, 0, 1.0f, 0);
        add(10, x,      pxt,           524288, 0, 0, 1.0f, 0);
        add(11, cross,  pct,           1048576, 0, 0, 1.0f, 0);
        add(12, ca_bq,  pfb + FB_CAQ,         128, 0, 0, SC,   2);
        add(13, ca_bk,  pfb + FB_CKV,         128, 0, 0, 1.0f, 2);
        add(14, ca_bv,  pfb + FB_CKV + 512,   128, 0, 0, 1.0f, 2);
        add(15, sa_bq,  pfb + FB_SQKV,        128, 0, 0, SC,   2);
        add(16, sa_bk,  pfb + FB_SQKV + 512,  128, 0, 0, 1.0f, 2);
        add(17, sa_bv,  pfb + FB_SQKV + 1024, 128, 0, 0, 1.0f, 2);
        pa.total = base;
        prep_kernel<<<(pa.total + 255) / 256, 256>>>(pa);
    }

    const int CMB_BLOCKS = (MQ * DMODEL / 4 + 255) / 256;

    // ---- cross attention ----  (Q/K/V emitted as fp16)
    launch_tc(pxt, pwt + WT_CAQ, pfb + FB_CAQ, nullptr, pqh, MQ, 512, DMODEL, 0, 2);
    launch_tc(pct, pwt + WT_CKV, pfb + FB_CKV, nullptr, pkvh, MK, 1024, DMODEL, 0, 2);
    {
        dim3 grid(NQ / 128, NHEADS, BATCH * NSPLIT);
        attn_kernel<<<grid, 128, ATTN_SMEM>>>(pqh, pkvh, pkvh + 512, pca, pcb, pls,
                                              NQ, NK, NK / NSPLIT, 512, 1024);
    }
    combine_kernel<<<CMB_BLOCKS, 256>>>((const float4*)pca, (const float4*)pcb,
                                        pls, pls + MQ * NHEADS, (uint4*)pcm);
    launch_tc(pcm, pwt + WT_CAO, ca_bo, nullptr, pxc, MQ, DMODEL, DMODEL, 0, 0);

    // ---- LN1 + self attention ----
    ln_kernel<<<MQ, 128>>>(pxc, ln1_g, ln1_b, pxn, 1);
    launch_tc(pxn, pwt + WT_SQKV, pfb + FB_SQKV, nullptr, pqkvh, MQ, 1536, DMODEL, 0, 2);
    {
        dim3 grid(NQ / 128, NHEADS, BATCH * NSPLIT);
        attn_kernel<<<grid, 128, ATTN_SMEM>>>(pqkvh, pqkvh + 512, pqkvh + 1024,
                                              pca, pcb, pls,
                                              NQ, NQ, NQ / NSPLIT, 1536, 1536);
    }
    combine_kernel<<<CMB_BLOCKS, 256>>>((const float4*)pca, (const float4*)pcb,
                                        pls, pls + MQ * NHEADS, (uint4*)pcm);
    launch_tc(pcm, pwt + WT_SAO, sa_bo, pxc, py, MQ, DMODEL, DMODEL, 0, 0);

    // ---- LN2 + MLP ----
    ln_kernel<<<MQ, 128>>>(py, ln2_g, ln2_b, pyn, 1);
    launch_tc(pyn, pwt + WT_M1, mlp_b1, nullptr, ph1, MQ, HID, DMODEL, 1, 1);
    launch_tc(ph1, pwt + WT_M2, mlp_b2, py, out, MQ, DMODEL, HID, 0, 0);
}